// round 2
// baseline (speedup 1.0000x reference)
#include <cuda_runtime.h>
#include <math.h>

#define NN 10000
#define DD 128
#define KSEL 5000
#define HALF_N 5000

// d_out layout (float32): x_pool[5000*128] | adj_pool[5000*5000] | motif_pool[5000*5000] | scores[10000] | top_idx[5000]
#define XP_OFF   0LL
#define ADJ_OFF  640000LL
#define MOT_OFF  (640000LL + 25000000LL)
#define SC_OFF   (640000LL + 50000000LL)
#define IDX_OFF  (SC_OFF + 10000LL)

// ---------------- scratch (device globals: no runtime allocation allowed) ----------------
__device__ float g_colpart[8][NN];
__device__ float g_dinv[NN];
__device__ float g_P[NN * DD];          // dinv_i * (x @ W^T)
__device__ float g_Gpart[2][NN * DD];   // split-K partial sums (deterministic, no atomics)
__device__ float g_h[NN * DD];
__device__ float g_scores[NN];
__device__ int   g_sel[NN];
__device__ int   g_idx[KSEL];

typedef unsigned long long u64;

__device__ __forceinline__ void ffma2(u64& d, u64 a, u64 b) {
    asm("fma.rn.f32x2 %0, %1, %2, %0;" : "+l"(d) : "l"(a), "l"(b));
}
__device__ __forceinline__ u64 pack2(float lo, float hi) {
    u64 r; asm("mov.b64 %0, {%1, %2};" : "=l"(r) : "f"(lo), "f"(hi)); return r;
}

// ---------------- 1) column partial sums of motif ----------------
__global__ __launch_bounds__(256) void colsum_kernel(const float* __restrict__ motif) {
    int j = blockIdx.x * 256 + threadIdx.x;
    if (j >= NN) return;
    int part = blockIdx.y;
    int r0 = part * (NN / 8);
    int r1 = r0 + (NN / 8);
    float s0 = 0.f, s1 = 0.f, s2 = 0.f, s3 = 0.f;
    int i = r0;
    for (; i + 3 < r1; i += 4) {
        s0 += motif[(size_t)(i + 0) * NN + j];
        s1 += motif[(size_t)(i + 1) * NN + j];
        s2 += motif[(size_t)(i + 2) * NN + j];
        s3 += motif[(size_t)(i + 3) * NN + j];
    }
    for (; i < r1; i++) s0 += motif[(size_t)i * NN + j];
    g_colpart[part][j] = (s0 + s1) + (s2 + s3);
}

// ---------------- 2) deg -> dinv ----------------
__global__ __launch_bounds__(256) void dinv_kernel() {
    int j = blockIdx.x * 256 + threadIdx.x;
    if (j >= NN) return;
    float d = 1.0f;  // +I diagonal contribution
    #pragma unroll
    for (int p = 0; p < 8; p++) d += g_colpart[p][j];
    g_dinv[j] = 1.0f / sqrtf(d);   // deg >= 1 always
}

// ---------------- 3) P[i,d] = dinv[i] * sum_e x[i,e] * W[d,e] ----------------
__global__ __launch_bounds__(128) void compute_P_kernel(const float* __restrict__ x,
                                                        const float* __restrict__ W) {
    __shared__ float smX[16][128];
    int tid = threadIdx.x;   // = d
    int i0 = blockIdx.x * 16;
    for (int f = tid; f < 16 * 32; f += 128) {
        int r = f >> 5, c = (f & 31) * 4;
        int gi = i0 + r;
        float4 v = (gi < NN) ? *(const float4*)&x[(size_t)gi * DD + c]
                             : make_float4(0.f, 0.f, 0.f, 0.f);
        *(float4*)&smX[r][c] = v;
    }
    __syncthreads();
    float acc[16];
    #pragma unroll
    for (int r = 0; r < 16; r++) acc[r] = 0.f;
    const float* wrow = W + (size_t)tid * DD;
    for (int e = 0; e < DD; e += 4) {
        float4 w4 = *(const float4*)&wrow[e];
        #pragma unroll
        for (int r = 0; r < 16; r++) {
            float4 x4 = *(const float4*)&smX[r][e];
            acc[r] += x4.x * w4.x + x4.y * w4.y + x4.z * w4.z + x4.w * w4.w;
        }
    }
    #pragma unroll
    for (int r = 0; r < 16; r++) {
        int gi = i0 + r;
        if (gi < NN) g_P[(size_t)gi * DD + tid] = g_dinv[gi] * acc[r];
    }
}

// ---------------- 4) G[j,d] = sum_i motif[i,j] * P[i,d]   (split-K over blockIdx.y) ----------------
__global__ __launch_bounds__(256, 2) void gemm_kernel(const float* __restrict__ motif) {
    __shared__ float smA[2][16][128];
    __shared__ float smB[2][16][128];
    const int tid = threadIdx.x;
    const int j0 = blockIdx.x * 128;
    const int split = blockIdx.y;
    const int kbeg = split * HALF_N;
    const int kend = kbeg + HALF_N;
    const int ntiles = (HALF_N + 15) / 16;

    const int tx = tid & 15;
    const int ty = tid >> 4;
    const int lr0 = tid >> 5;
    const int lr1 = lr0 + 8;
    const int lc  = (tid & 31) * 4;
    const bool jok = (j0 + lc) < NN;   // NN%4==0, lc%4==0: whole float4 in-range iff true

    u64 acc[8][4];
    #pragma unroll
    for (int m = 0; m < 8; m++)
        #pragma unroll
        for (int n = 0; n < 4; n++) acc[m][n] = 0ULL;

    const float4 z4 = make_float4(0.f, 0.f, 0.f, 0.f);
    float4 a0s, a1s, b0s, b1s;

    {   // prologue: tile 0
        int r0g = kbeg + lr0, r1g = kbeg + lr1;
        a0s = (jok && r0g < kend) ? *(const float4*)(motif + (size_t)r0g * NN + j0 + lc) : z4;
        a1s = (jok && r1g < kend) ? *(const float4*)(motif + (size_t)r1g * NN + j0 + lc) : z4;
        b0s = (r0g < kend) ? *(const float4*)(g_P + (size_t)r0g * DD + lc) : z4;
        b1s = (r1g < kend) ? *(const float4*)(g_P + (size_t)r1g * DD + lc) : z4;
        *(float4*)&smA[0][lr0][lc] = a0s;
        *(float4*)&smA[0][lr1][lc] = a1s;
        *(float4*)&smB[0][lr0][lc] = b0s;
        *(float4*)&smB[0][lr1][lc] = b1s;
    }
    __syncthreads();

    for (int t = 0; t < ntiles; t++) {
        int cur = t & 1;
        if (t + 1 < ntiles) {
            int base = kbeg + (t + 1) * 16;
            int r0g = base + lr0, r1g = base + lr1;
            a0s = (jok && r0g < kend) ? *(const float4*)(motif + (size_t)r0g * NN + j0 + lc) : z4;
            a1s = (jok && r1g < kend) ? *(const float4*)(motif + (size_t)r1g * NN + j0 + lc) : z4;
            b0s = (r0g < kend) ? *(const float4*)(g_P + (size_t)r0g * DD + lc) : z4;
            b1s = (r1g < kend) ? *(const float4*)(g_P + (size_t)r1g * DD + lc) : z4;
        }
        #pragma unroll
        for (int kk = 0; kk < 16; kk++) {
            float4 a0 = *(const float4*)&smA[cur][kk][tx * 4];
            float4 a1 = *(const float4*)&smA[cur][kk][64 + tx * 4];
            const u64* brow = (const u64*)&smB[cur][kk][0];
            u64 bp0 = brow[ty * 2], bp1 = brow[ty * 2 + 1];
            u64 bp2 = brow[32 + ty * 2], bp3 = brow[33 + ty * 2];
            float av[8] = {a0.x, a0.y, a0.z, a0.w, a1.x, a1.y, a1.z, a1.w};
            #pragma unroll
            for (int m = 0; m < 8; m++) {
                u64 ap = pack2(av[m], av[m]);
                ffma2(acc[m][0], ap, bp0);
                ffma2(acc[m][1], ap, bp1);
                ffma2(acc[m][2], ap, bp2);
                ffma2(acc[m][3], ap, bp3);
            }
        }
        if (t + 1 < ntiles) {
            int nb = (t + 1) & 1;
            *(float4*)&smA[nb][lr0][lc] = a0s;
            *(float4*)&smA[nb][lr1][lc] = a1s;
            *(float4*)&smB[nb][lr0][lc] = b0s;
            *(float4*)&smB[nb][lr1][lc] = b1s;
        }
        __syncthreads();
    }

    float* Gp = g_Gpart[split];
    #pragma unroll
    for (int m = 0; m < 8; m++) {
        int j = j0 + ((m < 4) ? (tx * 4 + m) : (64 + tx * 4 + (m - 4)));
        if (j < NN) {
            u64* d0 = (u64*)(Gp + (size_t)j * DD + ty * 4);
            d0[0] = acc[m][0]; d0[1] = acc[m][1];
            u64* d1 = (u64*)(Gp + (size_t)j * DD + 64 + ty * 4);
            d1[0] = acc[m][2]; d1[1] = acc[m][3];
        }
    }
}

// ---------------- 5) h = tanh(dinv_j*(G0+G1+P_j) + b);  scores = h @ w_score + b_score ----------------
__global__ __launch_bounds__(128) void epilogue_kernel(const float* __restrict__ b_gcn,
                                                       const float* __restrict__ w_score,
                                                       const float* __restrict__ b_score,
                                                       float* __restrict__ out) {
    int j = blockIdx.x;
    int d = threadIdx.x;
    size_t o = (size_t)j * DD + d;
    float g = g_Gpart[0][o] + g_Gpart[1][o] + g_P[o];
    float hv = tanhf(g_dinv[j] * g + b_gcn[d]);
    g_h[o] = hv;
    float v = hv * w_score[d];
    #pragma unroll
    for (int off = 16; off > 0; off >>= 1) v += __shfl_down_sync(0xffffffffu, v, off);
    __shared__ float ws[4];
    if ((d & 31) == 0) ws[d >> 5] = v;
    __syncthreads();
    if (d == 0) {
        float sc = ((ws[0] + ws[1]) + (ws[2] + ws[3])) + b_score[0];
        g_scores[j] = sc;
        out[SC_OFF + j] = sc;
    }
}

// ---------------- 6) top-k selection via exact rank (matches lax.top_k stable ties) ----------------
__global__ __launch_bounds__(256) void topk_rank_kernel() {
    __shared__ float ss[NN];
    int tid = threadIdx.x;
    for (int f = tid; f < NN; f += 256) ss[f] = g_scores[f];
    __syncthreads();
    int j = blockIdx.x * 256 + tid;
    if (j >= NN) return;
    float sj = ss[j];
    int rank = 0;
    for (int i = 0; i < NN; i++) {
        float si = ss[i];
        rank += (si > sj) ? 1 : ((si == sj && i < j) ? 1 : 0);
    }
    g_sel[j] = (rank < KSEL) ? 1 : 0;
}

// ---------------- 7) compact selected indices (ascending) ----------------
__global__ __launch_bounds__(256) void compact_kernel(float* __restrict__ out) {
    __shared__ int wsum[8];
    __shared__ int carry;
    int tid = threadIdx.x, lane = tid & 31, wid = tid >> 5;
    if (tid == 0) carry = 0;
    __syncthreads();
    for (int base = 0; base < NN; base += 256) {
        int j = base + tid;
        int f = (j < NN) ? g_sel[j] : 0;
        int xv = f;
        #pragma unroll
        for (int o = 1; o < 32; o <<= 1) {
            int y = __shfl_up_sync(0xffffffffu, xv, o);
            if (lane >= o) xv += y;
        }
        if (lane == 31) wsum[wid] = xv;
        __syncthreads();
        int woff = 0;
        #pragma unroll
        for (int w = 0; w < 8; w++) if (w < wid) woff += wsum[w];
        int incl = xv + woff;
        int pos = carry + incl - f;
        if (f) {
            g_idx[pos] = j;
            out[IDX_OFF + pos] = (float)j;
        }
        __syncthreads();
        if (tid == 255) carry += incl;   // incl of last thread == chunk total
        __syncthreads();
    }
}

// ---------------- 8) gather x_pool = h[top_idx] ----------------
__global__ __launch_bounds__(128) void gather_x_kernel(float* __restrict__ out) {
    int r = blockIdx.x;
    int d = threadIdx.x;
    int ir = g_idx[r];
    out[XP_OFF + (size_t)r * DD + d] = g_h[(size_t)ir * DD + d];
}

// ---------------- 9) gather adjacency/motif pools ----------------
__global__ __launch_bounds__(256) void gather_pools_kernel(const float* __restrict__ adj,
                                                           const float* __restrict__ motif,
                                                           float* __restrict__ out) {
    int r = blockIdx.x;
    int ir = g_idx[r];
    const float* arow = adj   + (size_t)ir * NN;
    const float* mrow = motif + (size_t)ir * NN;
    float* oa = out + ADJ_OFF + (size_t)r * KSEL;
    float* om = out + MOT_OFF + (size_t)r * KSEL;
    for (int c = threadIdx.x; c < KSEL; c += 256) {
        int ic = g_idx[c];
        oa[c] = arow[ic];
        om[c] = mrow[ic];
    }
}

// ---------------- launch ----------------
extern "C" void kernel_launch(void* const* d_in, const int* in_sizes, int n_in,
                              void* d_out, int out_size) {
    const float* x       = (const float*)d_in[0];
    const float* adj     = (const float*)d_in[1];
    const float* motif   = (const float*)d_in[2];
    const float* W       = (const float*)d_in[3];
    const float* b_gcn   = (const float*)d_in[4];
    const float* w_score = (const float*)d_in[5];
    const float* b_score = (const float*)d_in[6];
    float* out = (float*)d_out;

    colsum_kernel<<<dim3((NN + 255) / 256, 8), 256>>>(motif);
    dinv_kernel<<<(NN + 255) / 256, 256>>>();
    compute_P_kernel<<<NN / 16, 128>>>(x, W);
    gemm_kernel<<<dim3((NN + 127) / 128, 2), 256>>>(motif);
    epilogue_kernel<<<NN, 128>>>(b_gcn, w_score, b_score, out);
    topk_rank_kernel<<<(NN + 255) / 256, 256>>>();
    compact_kernel<<<1, 256>>>(out);
    gather_x_kernel<<<KSEL, 128>>>(out);
    gather_pools_kernel<<<KSEL, 256>>>(adj, motif, out);
}

// round 3
// speedup vs baseline: 1.0010x; 1.0010x over previous
#include <cuda_runtime.h>
#include <math.h>

#define NN 10000
#define DD 128
#define KSEL 5000
#define HALF_N 5000

// d_out layout (float32): x_pool[5000*128] | adj_pool[5000*5000] | motif_pool[5000*5000] | scores[10000] | top_idx[5000]
#define XP_OFF   0LL
#define ADJ_OFF  640000LL
#define MOT_OFF  (640000LL + 25000000LL)
#define SC_OFF   (640000LL + 50000000LL)
#define IDX_OFF  (SC_OFF + 10000LL)

// ---------------- scratch (device globals: no runtime allocation allowed) ----------------
__device__ float g_colpart[8][NN];
__device__ float g_dinv[NN];
__device__ float g_P[NN * DD];          // dinv_i * (x @ W^T)
__device__ float g_Gpart[2][NN * DD];   // split-K partial sums (deterministic, no atomics)
__device__ float g_h[NN * DD];
__device__ float g_scores[NN];
__device__ int   g_sel[NN];
__device__ int   g_idx[KSEL];

typedef unsigned long long u64;

__device__ __forceinline__ void ffma2(u64& d, u64 a, u64 b) {
    asm("fma.rn.f32x2 %0, %1, %2, %0;" : "+l"(d) : "l"(a), "l"(b));
}
__device__ __forceinline__ u64 pack2(float lo, float hi) {
    u64 r; asm("mov.b64 %0, {%1, %2};" : "=l"(r) : "f"(lo), "f"(hi)); return r;
}

// ---------------- 1) column partial sums of motif ----------------
__global__ __launch_bounds__(256) void colsum_kernel(const float* __restrict__ motif) {
    int j = blockIdx.x * 256 + threadIdx.x;
    if (j >= NN) return;
    int part = blockIdx.y;
    int r0 = part * (NN / 8);
    int r1 = r0 + (NN / 8);
    float s0 = 0.f, s1 = 0.f, s2 = 0.f, s3 = 0.f;
    int i = r0;
    for (; i + 3 < r1; i += 4) {
        s0 += motif[(size_t)(i + 0) * NN + j];
        s1 += motif[(size_t)(i + 1) * NN + j];
        s2 += motif[(size_t)(i + 2) * NN + j];
        s3 += motif[(size_t)(i + 3) * NN + j];
    }
    for (; i < r1; i++) s0 += motif[(size_t)i * NN + j];
    g_colpart[part][j] = (s0 + s1) + (s2 + s3);
}

// ---------------- 2) deg -> dinv ----------------
__global__ __launch_bounds__(256) void dinv_kernel() {
    int j = blockIdx.x * 256 + threadIdx.x;
    if (j >= NN) return;
    float d = 1.0f;  // +I diagonal contribution
    #pragma unroll
    for (int p = 0; p < 8; p++) d += g_colpart[p][j];
    g_dinv[j] = 1.0f / sqrtf(d);   // deg >= 1 always
}

// ---------------- 3) P[i,d] = dinv[i] * sum_e x[i,e] * W[d,e] ----------------
__global__ __launch_bounds__(128) void compute_P_kernel(const float* __restrict__ x,
                                                        const float* __restrict__ W) {
    __shared__ float smX[16][128];
    int tid = threadIdx.x;   // = d
    int i0 = blockIdx.x * 16;
    for (int f = tid; f < 16 * 32; f += 128) {
        int r = f >> 5, c = (f & 31) * 4;
        int gi = i0 + r;
        float4 v = (gi < NN) ? *(const float4*)&x[(size_t)gi * DD + c]
                             : make_float4(0.f, 0.f, 0.f, 0.f);
        *(float4*)&smX[r][c] = v;
    }
    __syncthreads();
    float acc[16];
    #pragma unroll
    for (int r = 0; r < 16; r++) acc[r] = 0.f;
    const float* wrow = W + (size_t)tid * DD;
    for (int e = 0; e < DD; e += 4) {
        float4 w4 = *(const float4*)&wrow[e];
        #pragma unroll
        for (int r = 0; r < 16; r++) {
            float4 x4 = *(const float4*)&smX[r][e];
            acc[r] += x4.x * w4.x + x4.y * w4.y + x4.z * w4.z + x4.w * w4.w;
        }
    }
    #pragma unroll
    for (int r = 0; r < 16; r++) {
        int gi = i0 + r;
        if (gi < NN) g_P[(size_t)gi * DD + tid] = g_dinv[gi] * acc[r];
    }
}

// ---------------- 4) G[j,d] = sum_i motif[i,j] * P[i,d]   (split-K over blockIdx.y) ----------------
__global__ __launch_bounds__(256, 2) void gemm_kernel(const float* __restrict__ motif) {
    __shared__ float smA[2][16][128];
    __shared__ float smB[2][16][128];
    const int tid = threadIdx.x;
    const int j0 = blockIdx.x * 128;
    const int split = blockIdx.y;
    const int kbeg = split * HALF_N;
    const int kend = kbeg + HALF_N;
    const int ntiles = (HALF_N + 15) / 16;

    const int tx = tid & 15;
    const int ty = tid >> 4;
    const int lr0 = tid >> 5;
    const int lr1 = lr0 + 8;
    const int lc  = (tid & 31) * 4;
    const bool jok = (j0 + lc) < NN;   // NN%4==0, lc%4==0: whole float4 in-range iff true

    u64 acc[8][4];
    #pragma unroll
    for (int m = 0; m < 8; m++)
        #pragma unroll
        for (int n = 0; n < 4; n++) acc[m][n] = 0ULL;

    const float4 z4 = make_float4(0.f, 0.f, 0.f, 0.f);
    float4 a0s, a1s, b0s, b1s;

    {   // prologue: tile 0
        int r0g = kbeg + lr0, r1g = kbeg + lr1;
        a0s = (jok && r0g < kend) ? *(const float4*)(motif + (size_t)r0g * NN + j0 + lc) : z4;
        a1s = (jok && r1g < kend) ? *(const float4*)(motif + (size_t)r1g * NN + j0 + lc) : z4;
        b0s = (r0g < kend) ? *(const float4*)(g_P + (size_t)r0g * DD + lc) : z4;
        b1s = (r1g < kend) ? *(const float4*)(g_P + (size_t)r1g * DD + lc) : z4;
        *(float4*)&smA[0][lr0][lc] = a0s;
        *(float4*)&smA[0][lr1][lc] = a1s;
        *(float4*)&smB[0][lr0][lc] = b0s;
        *(float4*)&smB[0][lr1][lc] = b1s;
    }
    __syncthreads();

    for (int t = 0; t < ntiles; t++) {
        int cur = t & 1;
        if (t + 1 < ntiles) {
            int base = kbeg + (t + 1) * 16;
            int r0g = base + lr0, r1g = base + lr1;
            a0s = (jok && r0g < kend) ? *(const float4*)(motif + (size_t)r0g * NN + j0 + lc) : z4;
            a1s = (jok && r1g < kend) ? *(const float4*)(motif + (size_t)r1g * NN + j0 + lc) : z4;
            b0s = (r0g < kend) ? *(const float4*)(g_P + (size_t)r0g * DD + lc) : z4;
            b1s = (r1g < kend) ? *(const float4*)(g_P + (size_t)r1g * DD + lc) : z4;
        }
        #pragma unroll
        for (int kk = 0; kk < 16; kk++) {
            float4 a0 = *(const float4*)&smA[cur][kk][tx * 4];
            float4 a1 = *(const float4*)&smA[cur][kk][64 + tx * 4];
            const u64* brow = (const u64*)&smB[cur][kk][0];
            u64 bp0 = brow[ty * 2], bp1 = brow[ty * 2 + 1];
            u64 bp2 = brow[32 + ty * 2], bp3 = brow[33 + ty * 2];
            float av[8] = {a0.x, a0.y, a0.z, a0.w, a1.x, a1.y, a1.z, a1.w};
            #pragma unroll
            for (int m = 0; m < 8; m++) {
                u64 ap = pack2(av[m], av[m]);
                ffma2(acc[m][0], ap, bp0);
                ffma2(acc[m][1], ap, bp1);
                ffma2(acc[m][2], ap, bp2);
                ffma2(acc[m][3], ap, bp3);
            }
        }
        if (t + 1 < ntiles) {
            int nb = (t + 1) & 1;
            *(float4*)&smA[nb][lr0][lc] = a0s;
            *(float4*)&smA[nb][lr1][lc] = a1s;
            *(float4*)&smB[nb][lr0][lc] = b0s;
            *(float4*)&smB[nb][lr1][lc] = b1s;
        }
        __syncthreads();
    }

    float* Gp = g_Gpart[split];
    #pragma unroll
    for (int m = 0; m < 8; m++) {
        int j = j0 + ((m < 4) ? (tx * 4 + m) : (64 + tx * 4 + (m - 4)));
        if (j < NN) {
            u64* d0 = (u64*)(Gp + (size_t)j * DD + ty * 4);
            d0[0] = acc[m][0]; d0[1] = acc[m][1];
            u64* d1 = (u64*)(Gp + (size_t)j * DD + 64 + ty * 4);
            d1[0] = acc[m][2]; d1[1] = acc[m][3];
        }
    }
}

// ---------------- 5) h = tanh(dinv_j*(G0+G1+P_j) + b);  scores = h @ w_score + b_score ----------------
__global__ __launch_bounds__(128) void epilogue_kernel(const float* __restrict__ b_gcn,
                                                       const float* __restrict__ w_score,
                                                       const float* __restrict__ b_score,
                                                       float* __restrict__ out) {
    int j = blockIdx.x;
    int d = threadIdx.x;
    size_t o = (size_t)j * DD + d;
    float g = g_Gpart[0][o] + g_Gpart[1][o] + g_P[o];
    float hv = tanhf(g_dinv[j] * g + b_gcn[d]);
    g_h[o] = hv;
    float v = hv * w_score[d];
    #pragma unroll
    for (int off = 16; off > 0; off >>= 1) v += __shfl_down_sync(0xffffffffu, v, off);
    __shared__ float ws[4];
    if ((d & 31) == 0) ws[d >> 5] = v;
    __syncthreads();
    if (d == 0) {
        float sc = ((ws[0] + ws[1]) + (ws[2] + ws[3])) + b_score[0];
        g_scores[j] = sc;
        out[SC_OFF + j] = sc;
    }
}

// ---------------- 6) top-k selection via exact rank (matches lax.top_k stable ties) ----------------
__global__ __launch_bounds__(256) void topk_rank_kernel() {
    __shared__ float ss[NN];
    int tid = threadIdx.x;
    for (int f = tid; f < NN; f += 256) ss[f] = g_scores[f];
    __syncthreads();
    int j = blockIdx.x * 256 + tid;
    if (j >= NN) return;
    float sj = ss[j];
    int rank = 0;
    for (int i = 0; i < NN; i++) {
        float si = ss[i];
        rank += (si > sj) ? 1 : ((si == sj && i < j) ? 1 : 0);
    }
    g_sel[j] = (rank < KSEL) ? 1 : 0;
}

// ---------------- 7) compact selected indices (ascending) ----------------
__global__ __launch_bounds__(256) void compact_kernel(float* __restrict__ out) {
    __shared__ int wsum[8];
    __shared__ int carry;
    int tid = threadIdx.x, lane = tid & 31, wid = tid >> 5;
    if (tid == 0) carry = 0;
    __syncthreads();
    for (int base = 0; base < NN; base += 256) {
        int j = base + tid;
        int f = (j < NN) ? g_sel[j] : 0;
        int xv = f;
        #pragma unroll
        for (int o = 1; o < 32; o <<= 1) {
            int y = __shfl_up_sync(0xffffffffu, xv, o);
            if (lane >= o) xv += y;
        }
        if (lane == 31) wsum[wid] = xv;
        __syncthreads();
        int woff = 0;
        #pragma unroll
        for (int w = 0; w < 8; w++) if (w < wid) woff += wsum[w];
        int incl = xv + woff;
        int pos = carry + incl - f;
        if (f) {
            g_idx[pos] = j;
            out[IDX_OFF + pos] = (float)j;
        }
        __syncthreads();
        if (tid == 255) carry += incl;   // incl of last thread == chunk total
        __syncthreads();
    }
}

// ---------------- 8) gather x_pool = h[top_idx] ----------------
__global__ __launch_bounds__(128) void gather_x_kernel(float* __restrict__ out) {
    int r = blockIdx.x;
    int d = threadIdx.x;
    int ir = g_idx[r];
    out[XP_OFF + (size_t)r * DD + d] = g_h[(size_t)ir * DD + d];
}

// ---------------- 9) gather adjacency/motif pools ----------------
__global__ __launch_bounds__(256) void gather_pools_kernel(const float* __restrict__ adj,
                                                           const float* __restrict__ motif,
                                                           float* __restrict__ out) {
    int r = blockIdx.x;
    int ir = g_idx[r];
    const float* arow = adj   + (size_t)ir * NN;
    const float* mrow = motif + (size_t)ir * NN;
    float* oa = out + ADJ_OFF + (size_t)r * KSEL;
    float* om = out + MOT_OFF + (size_t)r * KSEL;
    for (int c = threadIdx.x; c < KSEL; c += 256) {
        int ic = g_idx[c];
        oa[c] = arow[ic];
        om[c] = mrow[ic];
    }
}

// ---------------- launch ----------------
extern "C" void kernel_launch(void* const* d_in, const int* in_sizes, int n_in,
                              void* d_out, int out_size) {
    const float* x       = (const float*)d_in[0];
    const float* adj     = (const float*)d_in[1];
    const float* motif   = (const float*)d_in[2];
    const float* W       = (const float*)d_in[3];
    const float* b_gcn   = (const float*)d_in[4];
    const float* w_score = (const float*)d_in[5];
    const float* b_score = (const float*)d_in[6];
    float* out = (float*)d_out;

    colsum_kernel<<<dim3((NN + 255) / 256, 8), 256>>>(motif);
    dinv_kernel<<<(NN + 255) / 256, 256>>>();
    compute_P_kernel<<<NN / 16, 128>>>(x, W);
    gemm_kernel<<<dim3((NN + 127) / 128, 2), 256>>>(motif);
    epilogue_kernel<<<NN, 128>>>(b_gcn, w_score, b_score, out);
    topk_rank_kernel<<<(NN + 255) / 256, 256>>>();
    compact_kernel<<<1, 256>>>(out);
    gather_x_kernel<<<KSEL, 128>>>(out);
    gather_pools_kernel<<<KSEL, 256>>>(adj, motif, out);
}

// round 5
// speedup vs baseline: 1.5221x; 1.5206x over previous
#include <cuda_runtime.h>
#include <math.h>

#define NN 10000
#define DD 128
#define KSEL 5000
#define HALF_N 5000

// d_out layout (float32): x_pool[5000*128] | adj_pool[5000*5000] | motif_pool[5000*5000] | scores[10000] | top_idx[5000]
#define XP_OFF   0LL
#define ADJ_OFF  640000LL
#define MOT_OFF  (640000LL + 25000000LL)
#define SC_OFF   (640000LL + 50000000LL)
#define IDX_OFF  (SC_OFF + 10000LL)

// ---------------- scratch (device globals: no runtime allocation allowed) ----------------
__device__ float g_colpart[8][NN];
__device__ float g_dinv[NN];
__device__ float g_P[NN * DD];          // dinv_i * (x @ W^T)
__device__ float g_Gpart[2][NN * DD];   // split-K partial sums (deterministic, no atomics)
__device__ float g_h[NN * DD];
__device__ float g_scores[NN];
__device__ int   g_sel[NN];
__device__ int   g_idx[KSEL];

typedef unsigned long long u64;

__device__ __forceinline__ void ffma2(u64& d, u64 a, u64 b) {
    asm("fma.rn.f32x2 %0, %1, %2, %0;" : "+l"(d) : "l"(a), "l"(b));
}
__device__ __forceinline__ u64 pack2(float lo, float hi) {
    u64 r; asm("mov.b64 %0, {%1, %2};" : "=l"(r) : "f"(lo), "f"(hi)); return r;
}

// ---------------- 1) column partial sums of motif ----------------
__global__ __launch_bounds__(256) void colsum_kernel(const float* __restrict__ motif) {
    int j = blockIdx.x * 256 + threadIdx.x;
    if (j >= NN) return;
    int part = blockIdx.y;
    int r0 = part * (NN / 8);
    int r1 = r0 + (NN / 8);
    float s0 = 0.f, s1 = 0.f, s2 = 0.f, s3 = 0.f;
    int i = r0;
    for (; i + 3 < r1; i += 4) {
        s0 += motif[(size_t)(i + 0) * NN + j];
        s1 += motif[(size_t)(i + 1) * NN + j];
        s2 += motif[(size_t)(i + 2) * NN + j];
        s3 += motif[(size_t)(i + 3) * NN + j];
    }
    for (; i < r1; i++) s0 += motif[(size_t)i * NN + j];
    g_colpart[part][j] = (s0 + s1) + (s2 + s3);
}

// ---------------- 2) deg -> dinv ----------------
__global__ __launch_bounds__(256) void dinv_kernel() {
    int j = blockIdx.x * 256 + threadIdx.x;
    if (j >= NN) return;
    float d = 1.0f;  // +I diagonal contribution
    #pragma unroll
    for (int p = 0; p < 8; p++) d += g_colpart[p][j];
    g_dinv[j] = 1.0f / sqrtf(d);   // deg >= 1 always
}

// ---------------- 3) P[i,d] = dinv[i] * sum_e x[i,e] * W[d,e] ----------------
__global__ __launch_bounds__(128) void compute_P_kernel(const float* __restrict__ x,
                                                        const float* __restrict__ W) {
    __shared__ float smX[16][128];
    int tid = threadIdx.x;   // = d
    int i0 = blockIdx.x * 16;
    for (int f = tid; f < 16 * 32; f += 128) {
        int r = f >> 5, c = (f & 31) * 4;
        int gi = i0 + r;
        float4 v = (gi < NN) ? *(const float4*)&x[(size_t)gi * DD + c]
                             : make_float4(0.f, 0.f, 0.f, 0.f);
        *(float4*)&smX[r][c] = v;
    }
    __syncthreads();
    float acc[16];
    #pragma unroll
    for (int r = 0; r < 16; r++) acc[r] = 0.f;
    const float* wrow = W + (size_t)tid * DD;
    for (int e = 0; e < DD; e += 4) {
        float4 w4 = *(const float4*)&wrow[e];
        #pragma unroll
        for (int r = 0; r < 16; r++) {
            float4 x4 = *(const float4*)&smX[r][e];
            acc[r] += x4.x * w4.x + x4.y * w4.y + x4.z * w4.z + x4.w * w4.w;
        }
    }
    #pragma unroll
    for (int r = 0; r < 16; r++) {
        int gi = i0 + r;
        if (gi < NN) g_P[(size_t)gi * DD + tid] = g_dinv[gi] * acc[r];
    }
}

// ---------------- 4) G[j,d] = sum_i motif[i,j] * P[i,d]   (split-K over blockIdx.y) ----------------
__global__ __launch_bounds__(256, 2) void gemm_kernel(const float* __restrict__ motif) {
    __shared__ float smA[2][16][128];
    __shared__ float smB[2][16][128];
    const int tid = threadIdx.x;
    const int j0 = blockIdx.x * 128;
    const int split = blockIdx.y;
    const int kbeg = split * HALF_N;
    const int kend = kbeg + HALF_N;
    const int ntiles = (HALF_N + 15) / 16;

    const int tx = tid & 15;
    const int ty = tid >> 4;
    const int lr0 = tid >> 5;
    const int lr1 = lr0 + 8;
    const int lc  = (tid & 31) * 4;
    const bool jok = (j0 + lc) < NN;   // NN%4==0, lc%4==0: whole float4 in-range iff true

    u64 acc[8][4];
    #pragma unroll
    for (int m = 0; m < 8; m++)
        #pragma unroll
        for (int n = 0; n < 4; n++) acc[m][n] = 0ULL;

    const float4 z4 = make_float4(0.f, 0.f, 0.f, 0.f);
    float4 a0s, a1s, b0s, b1s;

    {   // prologue: tile 0
        int r0g = kbeg + lr0, r1g = kbeg + lr1;
        a0s = (jok && r0g < kend) ? *(const float4*)(motif + (size_t)r0g * NN + j0 + lc) : z4;
        a1s = (jok && r1g < kend) ? *(const float4*)(motif + (size_t)r1g * NN + j0 + lc) : z4;
        b0s = (r0g < kend) ? *(const float4*)(g_P + (size_t)r0g * DD + lc) : z4;
        b1s = (r1g < kend) ? *(const float4*)(g_P + (size_t)r1g * DD + lc) : z4;
        *(float4*)&smA[0][lr0][lc] = a0s;
        *(float4*)&smA[0][lr1][lc] = a1s;
        *(float4*)&smB[0][lr0][lc] = b0s;
        *(float4*)&smB[0][lr1][lc] = b1s;
    }
    __syncthreads();

    for (int t = 0; t < ntiles; t++) {
        int cur = t & 1;
        if (t + 1 < ntiles) {
            int base = kbeg + (t + 1) * 16;
            int r0g = base + lr0, r1g = base + lr1;
            a0s = (jok && r0g < kend) ? *(const float4*)(motif + (size_t)r0g * NN + j0 + lc) : z4;
            a1s = (jok && r1g < kend) ? *(const float4*)(motif + (size_t)r1g * NN + j0 + lc) : z4;
            b0s = (r0g < kend) ? *(const float4*)(g_P + (size_t)r0g * DD + lc) : z4;
            b1s = (r1g < kend) ? *(const float4*)(g_P + (size_t)r1g * DD + lc) : z4;
        }
        #pragma unroll
        for (int kk = 0; kk < 16; kk++) {
            float4 a0 = *(const float4*)&smA[cur][kk][tx * 4];
            float4 a1 = *(const float4*)&smA[cur][kk][64 + tx * 4];
            const u64* brow = (const u64*)&smB[cur][kk][0];
            u64 bp0 = brow[ty * 2], bp1 = brow[ty * 2 + 1];
            u64 bp2 = brow[32 + ty * 2], bp3 = brow[33 + ty * 2];
            float av[8] = {a0.x, a0.y, a0.z, a0.w, a1.x, a1.y, a1.z, a1.w};
            #pragma unroll
            for (int m = 0; m < 8; m++) {
                u64 ap = pack2(av[m], av[m]);
                ffma2(acc[m][0], ap, bp0);
                ffma2(acc[m][1], ap, bp1);
                ffma2(acc[m][2], ap, bp2);
                ffma2(acc[m][3], ap, bp3);
            }
        }
        if (t + 1 < ntiles) {
            int nb = (t + 1) & 1;
            *(float4*)&smA[nb][lr0][lc] = a0s;
            *(float4*)&smA[nb][lr1][lc] = a1s;
            *(float4*)&smB[nb][lr0][lc] = b0s;
            *(float4*)&smB[nb][lr1][lc] = b1s;
        }
        __syncthreads();
    }

    float* Gp = g_Gpart[split];
    #pragma unroll
    for (int m = 0; m < 8; m++) {
        int j = j0 + ((m < 4) ? (tx * 4 + m) : (64 + tx * 4 + (m - 4)));
        if (j < NN) {
            u64* d0 = (u64*)(Gp + (size_t)j * DD + ty * 4);
            d0[0] = acc[m][0]; d0[1] = acc[m][1];
            u64* d1 = (u64*)(Gp + (size_t)j * DD + 64 + ty * 4);
            d1[0] = acc[m][2]; d1[1] = acc[m][3];
        }
    }
}

// ---------------- 5) h = tanh(dinv_j*(G0+G1+P_j) + b);  scores = h @ w_score + b_score ----------------
__global__ __launch_bounds__(128) void epilogue_kernel(const float* __restrict__ b_gcn,
                                                       const float* __restrict__ w_score,
                                                       const float* __restrict__ b_score,
                                                       float* __restrict__ out) {
    int j = blockIdx.x;
    int d = threadIdx.x;
    size_t o = (size_t)j * DD + d;
    float g = g_Gpart[0][o] + g_Gpart[1][o] + g_P[o];
    float hv = tanhf(g_dinv[j] * g + b_gcn[d]);
    g_h[o] = hv;
    float v = hv * w_score[d];
    #pragma unroll
    for (int off = 16; off > 0; off >>= 1) v += __shfl_down_sync(0xffffffffu, v, off);
    __shared__ float ws[4];
    if ((d & 31) == 0) ws[d >> 5] = v;
    __syncthreads();
    if (d == 0) {
        float sc = ((ws[0] + ws[1]) + (ws[2] + ws[3])) + b_score[0];
        g_scores[j] = sc;
        out[SC_OFF + j] = sc;
    }
}

// ---------------- 6) top-k selection via exact rank (matches lax.top_k stable ties) ----------------
__global__ __launch_bounds__(256) void topk_rank_kernel() {
    __shared__ float ss[NN];
    int tid = threadIdx.x;
    for (int f = tid; f < NN; f += 256) ss[f] = g_scores[f];
    __syncthreads();
    int j = blockIdx.x * 256 + tid;
    if (j >= NN) return;
    float sj = ss[j];
    int rank = 0;
    for (int i = 0; i < NN; i++) {
        float si = ss[i];
        rank += (si > sj) ? 1 : ((si == sj && i < j) ? 1 : 0);
    }
    g_sel[j] = (rank < KSEL) ? 1 : 0;
}

// ---------------- 7) compact selected indices (ascending) ----------------
__global__ __launch_bounds__(256) void compact_kernel(float* __restrict__ out) {
    __shared__ int wsum[8];
    __shared__ int carry;
    int tid = threadIdx.x, lane = tid & 31, wid = tid >> 5;
    if (tid == 0) carry = 0;
    __syncthreads();
    for (int base = 0; base < NN; base += 256) {
        int j = base + tid;
        int f = (j < NN) ? g_sel[j] : 0;
        int xv = f;
        #pragma unroll
        for (int o = 1; o < 32; o <<= 1) {
            int y = __shfl_up_sync(0xffffffffu, xv, o);
            if (lane >= o) xv += y;
        }
        if (lane == 31) wsum[wid] = xv;
        __syncthreads();
        int woff = 0;
        #pragma unroll
        for (int w = 0; w < 8; w++) if (w < wid) woff += wsum[w];
        int incl = xv + woff;
        int pos = carry + incl - f;
        if (f) {
            g_idx[pos] = j;
            out[IDX_OFF + pos] = (float)j;
        }
        __syncthreads();
        if (tid == 255) carry += incl;   // incl of last thread == chunk total
        __syncthreads();
    }
}

// ---------------- 8) gather x_pool = h[top_idx] ----------------
__global__ __launch_bounds__(128) void gather_x_kernel(float* __restrict__ out) {
    int r = blockIdx.x;
    int d = threadIdx.x;
    int ir = g_idx[r];
    out[XP_OFF + (size_t)r * DD + d] = g_h[(size_t)ir * DD + d];
}

// ---------------- 9) gather adjacency/motif pools ----------------
__global__ __launch_bounds__(256) void gather_pools_kernel(const float* __restrict__ adj,
                                                           const float* __restrict__ motif,
                                                           float* __restrict__ out) {
    int r = blockIdx.x;
    int ir = g_idx[r];
    const float* arow = adj   + (size_t)ir * NN;
    const float* mrow = motif + (size_t)ir * NN;
    float* oa = out + ADJ_OFF + (size_t)r * KSEL;
    float* om = out + MOT_OFF + (size_t)r * KSEL;
    for (int c = threadIdx.x; c < KSEL; c += 256) {
        int ic = g_idx[c];
        oa[c] = arow[ic];
        om[c] = mrow[ic];
    }
}

// ---------------- launch ----------------
extern "C" void kernel_launch(void* const* d_in, const int* in_sizes, int n_in,
                              void* d_out, int out_size) {
    const float* x       = (const float*)d_in[0];
    const float* adj     = (const float*)d_in[1];
    const float* motif   = (const float*)d_in[2];
    const float* W       = (const float*)d_in[3];
    const float* b_gcn   = (const float*)d_in[4];
    const float* w_score = (const float*)d_in[5];
    const float* b_score = (const float*)d_in[6];
    float* out = (float*)d_out;

    colsum_kernel<<<dim3((NN + 255) / 256, 8), 256>>>(motif);
    dinv_kernel<<<(NN + 255) / 256, 256>>>();
    compute_P_kernel<<<NN / 16, 128>>>(x, W);
    gemm_kernel<<<dim3((NN + 127) / 128, 2), 256>>>(motif);
    epilogue_kernel<<<NN, 128>>>(b_gcn, w_score, b_score, out);
    topk_rank_kernel<<<(NN + 255) / 256, 256>>>();
    compact_kernel<<<1, 256>>>(out);
    gather_x_kernel<<<KSEL, 128>>>(out);
    gather_pools_kernel<<<KSEL, 256>>>(adj, motif, out);
}

// round 10
// speedup vs baseline: 2.9590x; 1.9440x over previous
#include <cuda_runtime.h>
#include <cuda_bf16.h>
#include <cstdint>
#include <math.h>

#define NN 10000
#define DD 128
#define KSEL 5000
#define BM 64
#define BK 32
#define NST 313                 // ceil(10000/32)
#define NKPAD (NST * BK)        // 10016
#define NSPLIT 4
#define NJT 157                 // ceil(10000/64)

// d_out layout (float32): x_pool[5000*128] | adj_pool[5000*5000] | motif_pool[5000*5000] | scores[10000] | top_idx[5000]
#define XP_OFF   0LL
#define ADJ_OFF  640000LL
#define MOT_OFF  (640000LL + 25000000LL)
#define SC_OFF   (640000LL + 50000000LL)
#define IDX_OFF  (SC_OFF + 10000LL)

// ---------------- scratch (device globals; zero-initialized at load) ----------------
__device__ float g_colpart[8][NN];
__device__ float g_dinv[NN];
__device__ float g_P[(size_t)NN * DD];                 // dinv_i * (x @ W^T), fp32
__device__ __nv_bfloat16 g_Pbh[(size_t)NKPAD * DD];    // P bf16 hi, [i][d], rows >= NN stay zero
__device__ __nv_bfloat16 g_Pbl[(size_t)NKPAD * DD];    // P bf16 lo
__device__ float g_Gpart[NSPLIT][(size_t)NN * DD];     // split-K partials
__device__ float g_h[(size_t)NN * DD];
__device__ float g_scores[NN];
__device__ int   g_sel[NN];
__device__ int   g_idx[KSEL];

// ---------------- PTX helpers (all sm_80-level: compile on compute_103 family target) ----------------
__device__ __forceinline__ uint32_t smem_u32(const void* p) {
    uint32_t a;
    asm("{ .reg .u64 t; cvta.to.shared.u64 t, %1; cvt.u32.u64 %0, t; }" : "=r"(a) : "l"(p));
    return a;
}
__device__ __forceinline__ void cpasync16(uint32_t dst, const void* src) {
    asm volatile("cp.async.cg.shared.global [%0], [%1], 16;" :: "r"(dst), "l"(src));
}
#define CP_COMMIT() asm volatile("cp.async.commit_group;" ::: "memory")
#define CP_WAIT(n)  asm volatile("cp.async.wait_group %0;" :: "n"(n) : "memory")

__device__ __forceinline__ void sts128(uint32_t addr, uint32_t a, uint32_t b, uint32_t c, uint32_t d) {
    asm volatile("st.shared.v4.b32 [%0], {%1,%2,%3,%4};" :: "r"(addr), "r"(a), "r"(b), "r"(c), "r"(d));
}
__device__ __forceinline__ void ldsm4t(uint32_t* r, uint32_t addr) {
    asm volatile("ldmatrix.sync.aligned.m8n8.x4.trans.shared.b16 {%0,%1,%2,%3}, [%4];"
        : "=r"(r[0]), "=r"(r[1]), "=r"(r[2]), "=r"(r[3]) : "r"(addr));
}
__device__ __forceinline__ void mma16816(float* c, const uint32_t* a, const uint32_t* b) {
    asm volatile("mma.sync.aligned.m16n8k16.row.col.f32.bf16.bf16.f32 "
        "{%0,%1,%2,%3}, {%4,%5,%6,%7}, {%8,%9}, {%0,%1,%2,%3};"
        : "+f"(c[0]), "+f"(c[1]), "+f"(c[2]), "+f"(c[3])
        : "r"(a[0]), "r"(a[1]), "r"(a[2]), "r"(a[3]), "r"(b[0]), "r"(b[1]));
}

// ---------------- 1) column partial sums of motif ----------------
__global__ __launch_bounds__(256) void colsum_kernel(const float* __restrict__ motif) {
    int j = blockIdx.x * 256 + threadIdx.x;
    if (j >= NN) return;
    int part = blockIdx.y;
    int r0 = part * (NN / 8);
    int r1 = r0 + (NN / 8);
    float s0 = 0.f, s1 = 0.f, s2 = 0.f, s3 = 0.f;
    int i = r0;
    for (; i + 3 < r1; i += 4) {
        s0 += motif[(size_t)(i + 0) * NN + j];
        s1 += motif[(size_t)(i + 1) * NN + j];
        s2 += motif[(size_t)(i + 2) * NN + j];
        s3 += motif[(size_t)(i + 3) * NN + j];
    }
    for (; i < r1; i++) s0 += motif[(size_t)i * NN + j];
    g_colpart[part][j] = (s0 + s1) + (s2 + s3);
}

// ---------------- 2) deg -> dinv ----------------
__global__ __launch_bounds__(256) void dinv_kernel() {
    int j = blockIdx.x * 256 + threadIdx.x;
    if (j >= NN) return;
    float d = 1.0f;  // +I diagonal
    #pragma unroll
    for (int p = 0; p < 8; p++) d += g_colpart[p][j];
    g_dinv[j] = 1.0f / sqrtf(d);
}

// ---------------- 3) P[i,d] = dinv[i]*(x@W^T); also emit bf16 hi/lo in [i][d] ----------------
__global__ __launch_bounds__(128) void compute_P_kernel(const float* __restrict__ x,
                                                        const float* __restrict__ W) {
    __shared__ float smX[16][128];
    int tid = threadIdx.x;   // = d
    int i0 = blockIdx.x * 16;
    for (int f = tid; f < 16 * 32; f += 128) {
        int r = f >> 5, c = (f & 31) * 4;
        *(float4*)&smX[r][c] = *(const float4*)&x[(size_t)(i0 + r) * DD + c];
    }
    __syncthreads();
    float acc[16];
    #pragma unroll
    for (int r = 0; r < 16; r++) acc[r] = 0.f;
    const float* wrow = W + (size_t)tid * DD;
    for (int e = 0; e < DD; e += 4) {
        float4 w4 = *(const float4*)&wrow[e];
        #pragma unroll
        for (int r = 0; r < 16; r++) {
            float4 x4 = *(const float4*)&smX[r][e];
            acc[r] += x4.x * w4.x + x4.y * w4.y + x4.z * w4.z + x4.w * w4.w;
        }
    }
    #pragma unroll
    for (int r = 0; r < 16; r++) {
        int gi = i0 + r;
        float p = g_dinv[gi] * acc[r];
        g_P[(size_t)gi * DD + tid] = p;
        __nv_bfloat16 hb = __float2bfloat16(p);
        g_Pbh[(size_t)gi * DD + tid] = hb;
        g_Pbl[(size_t)gi * DD + tid] = __float2bfloat16(p - __bfloat162float(hb));
    }
}

// ---------------- 4) HMMA GEMM: G[j,d] = sum_i motif[i,j]*P[i,d], bf16 hi/lo x3 ----------------
// A staged from fp32 motif (convert in-regs), [k][m] smem layout, XOR-16B swizzle, ldmatrix.trans.
// B staged via cp.async from g_Pbh/g_Pbl ([k][n]), same swizzle, ldmatrix.trans.
__global__ __launch_bounds__(256) void hmma_gemm_kernel(const float* __restrict__ motif) {
    extern __shared__ __align__(128) char dynsm[];
    const uint32_t smbase = smem_u32(dynsm);
    const uint32_t A_h = smbase;             // [2][32][64] bf16 : 2 x 4096B
    const uint32_t A_l = smbase + 8192;
    const uint32_t B_h = smbase + 16384;     // [2][32][128] bf16: 2 x 8192B
    const uint32_t B_l = smbase + 32768;     // total 49152B

    const int tid = threadIdx.x;
    const int lane = tid & 31;
    const int wid = tid >> 5;
    const int wm = wid & 1;      // 2 warp-rows (m)
    const int wn = wid >> 1;     // 4 warp-cols (n)
    const int j0 = blockIdx.x * BM;
    const int split = blockIdx.y;
    const int sbeg = split * 78 + (split ? 1 : 0);   // 0,79,157,235
    const int nstg = split ? 78 : 79;

    // A loader: thread -> (k row, 8-float j segment)
    const int ak = tid >> 3;
    const int aj = tid & 7;
    const bool jv = (j0 + aj * 8) < NN;              // NN % 8 == 0 -> whole segment validity
    const uint32_t aStOff = (uint32_t)ak * 128 + (uint32_t)(aj ^ (ak & 7)) * 16;
    const float* aSrcBase = motif + (size_t)j0 + (size_t)aj * 8;

    // B loader: thread -> (k row, chunks bc and bc+8)
    const int bk = tid >> 3;
    const int bc = tid & 7;
    const uint32_t bStOff0 = (uint32_t)bk * 256 + (uint32_t)(bc ^ (bk & 7)) * 16;
    const uint32_t bStOff1 = bStOff0 + 128;          // chunk+8 keeps bit3, low3 XOR same

    float4 areg[2][2];
    float acc[2][4][4];
    #pragma unroll
    for (int mt = 0; mt < 2; mt++)
        #pragma unroll
        for (int nt = 0; nt < 4; nt++)
            #pragma unroll
            for (int q = 0; q < 4; q++) acc[mt][nt][q] = 0.f;

    const float4 z4 = make_float4(0.f, 0.f, 0.f, 0.f);

#define LDG_A(t) do { \
    int _i = (sbeg + (t)) * BK + ak; \
    bool _v = jv && (_i < NN); \
    const float* _p = aSrcBase + (size_t)_i * NN; \
    areg[(t) & 1][0] = _v ? *(const float4*)_p : z4; \
    areg[(t) & 1][1] = _v ? *(const float4*)(_p + 4) : z4; \
} while (0)

#define STS_A(t) do { \
    float4 _v0 = areg[(t) & 1][0], _v1 = areg[(t) & 1][1]; \
    float _f[8] = {_v0.x, _v0.y, _v0.z, _v0.w, _v1.x, _v1.y, _v1.z, _v1.w}; \
    uint32_t _h[4], _l[4]; \
    _Pragma("unroll") \
    for (int _e = 0; _e < 4; _e++) { \
        __nv_bfloat16 _h0 = __float2bfloat16(_f[2 * _e]); \
        __nv_bfloat16 _h1 = __float2bfloat16(_f[2 * _e + 1]); \
        float _l0 = _f[2 * _e] - __bfloat162float(_h0); \
        float _l1 = _f[2 * _e + 1] - __bfloat162float(_h1); \
        __nv_bfloat162 _hp, _lp; \
        _hp.x = _h0; _hp.y = _h1; \
        _lp = __floats2bfloat162_rn(_l0, _l1); \
        _h[_e] = *(uint32_t*)&_hp; _l[_e] = *(uint32_t*)&_lp; \
    } \
    uint32_t _bo = ((t) & 1) * 4096u + aStOff; \
    sts128(A_h + _bo, _h[0], _h[1], _h[2], _h[3]); \
    sts128(A_l + _bo, _l[0], _l[1], _l[2], _l[3]); \
} while (0)

#define CP_B(t) do { \
    int _i = (sbeg + (t)) * BK + bk; \
    uint32_t _bb = ((t) & 1) * 8192u; \
    const __nv_bfloat16* _sh = g_Pbh + (size_t)_i * DD + bc * 8; \
    const __nv_bfloat16* _sl = g_Pbl + (size_t)_i * DD + bc * 8; \
    cpasync16(B_h + _bb + bStOff0, _sh); \
    cpasync16(B_h + _bb + bStOff1, _sh + 64); \
    cpasync16(B_l + _bb + bStOff0, _sl); \
    cpasync16(B_l + _bb + bStOff1, _sl + 64); \
    CP_COMMIT(); \
} while (0)

    // prologue
    LDG_A(0); CP_B(0); STS_A(0);
    LDG_A(1); CP_B(1);

    for (int t = 0; t < nstg; t++) {
        const int b = t & 1;
        if (t + 2 < nstg) LDG_A(t + 2);
        if (t + 1 < nstg) STS_A(t + 1);
        if (t + 1 < nstg) { CP_WAIT(1); } else { CP_WAIT(0); }
        __syncthreads();

        const uint32_t Ah = A_h + b * 4096u, Al = A_l + b * 4096u;
        const uint32_t Bh = B_h + b * 8192u, Bl = B_l + b * 8192u;
        #pragma unroll
        for (int kb = 0; kb < 2; kb++) {
            uint32_t ah[2][4], al[2][4], bh[2][4], bl[2][4];
            const int krA = kb * 16 + (lane & 7) + ((lane & 16) ? 8 : 0);
            #pragma unroll
            for (int mt = 0; mt < 2; mt++) {
                uint32_t ch = (uint32_t)((wm * 4 + mt * 2 + ((lane & 8) ? 1 : 0)) ^ (krA & 7));
                uint32_t ad = (uint32_t)krA * 128 + ch * 16;
                ldsm4t(ah[mt], Ah + ad);
                ldsm4t(al[mt], Al + ad);
            }
            const int krB = kb * 16 + (lane & 7) + ((lane & 8) ? 8 : 0);
            #pragma unroll
            for (int np = 0; np < 2; np++) {
                uint32_t c = (uint32_t)(wn * 4 + np * 2 + ((lane & 16) ? 1 : 0));
                uint32_t csw = (c & 8u) | ((c ^ (uint32_t)krB) & 7u);
                uint32_t bd = (uint32_t)krB * 256 + csw * 16;
                ldsm4t(bh[np], Bh + bd);
                ldsm4t(bl[np], Bl + bd);
            }
            #pragma unroll
            for (int mt = 0; mt < 2; mt++)
                #pragma unroll
                for (int nt = 0; nt < 4; nt++) {
                    const int np = nt >> 1, hf = nt & 1;
                    uint32_t bhp[2] = {bh[np][hf * 2], bh[np][hf * 2 + 1]};
                    uint32_t blp[2] = {bl[np][hf * 2], bl[np][hf * 2 + 1]};
                    mma16816(acc[mt][nt], ah[mt], bhp);   // hi*hi
                    mma16816(acc[mt][nt], ah[mt], blp);   // hi*lo
                    mma16816(acc[mt][nt], al[mt], bhp);   // lo*hi
                }
        }
        __syncthreads();
        if (t + 2 < nstg) CP_B(t + 2);
    }

    // store partial G
    float* G = g_Gpart[split];
    #pragma unroll
    for (int mt = 0; mt < 2; mt++)
        #pragma unroll
        for (int nt = 0; nt < 4; nt++) {
            int j = j0 + wm * 32 + mt * 16 + (lane >> 2);
            int d = wn * 32 + nt * 8 + (lane & 3) * 2;
            if (j < NN) {
                float2 v = make_float2(acc[mt][nt][0], acc[mt][nt][1]);
                *(float2*)(G + (size_t)j * DD + d) = v;
            }
            if (j + 8 < NN) {
                float2 v = make_float2(acc[mt][nt][2], acc[mt][nt][3]);
                *(float2*)(G + (size_t)(j + 8) * DD + d) = v;
            }
        }
#undef LDG_A
#undef STS_A
#undef CP_B
}

// ---------------- 5) h = tanh(dinv_j*(sum G + P_j) + b); scores ----------------
__global__ __launch_bounds__(128) void epilogue_kernel(const float* __restrict__ b_gcn,
                                                       const float* __restrict__ w_score,
                                                       const float* __restrict__ b_score,
                                                       float* __restrict__ out) {
    int j = blockIdx.x;
    int d = threadIdx.x;
    size_t o = (size_t)j * DD + d;
    float g = ((g_Gpart[0][o] + g_Gpart[1][o]) + (g_Gpart[2][o] + g_Gpart[3][o])) + g_P[o];
    float hv = tanhf(g_dinv[j] * g + b_gcn[d]);
    g_h[o] = hv;
    float v = hv * w_score[d];
    #pragma unroll
    for (int off = 16; off > 0; off >>= 1) v += __shfl_down_sync(0xffffffffu, v, off);
    __shared__ float ws[4];
    if ((d & 31) == 0) ws[d >> 5] = v;
    __syncthreads();
    if (d == 0) {
        float sc = ((ws[0] + ws[1]) + (ws[2] + ws[3])) + b_score[0];
        g_scores[j] = sc;
        out[SC_OFF + j] = sc;
    }
}

// ---------------- 6) top-k via exact rank (matches lax.top_k stable ties) ----------------
__global__ __launch_bounds__(256) void topk_rank_kernel() {
    __shared__ float ss[NN];
    int tid = threadIdx.x;
    for (int f = tid; f < NN; f += 256) ss[f] = g_scores[f];
    __syncthreads();
    int j = blockIdx.x * 256 + tid;
    if (j >= NN) return;
    float sj = ss[j];
    int rank = 0;
    for (int i = 0; i < NN; i++) {
        float si = ss[i];
        rank += (si > sj) ? 1 : ((si == sj && i < j) ? 1 : 0);
    }
    g_sel[j] = (rank < KSEL) ? 1 : 0;
}

// ---------------- 7) compact selected indices (ascending) ----------------
__global__ __launch_bounds__(256) void compact_kernel(float* __restrict__ out) {
    __shared__ int wsum[8];
    __shared__ int carry;
    int tid = threadIdx.x, lane = tid & 31, wid = tid >> 5;
    if (tid == 0) carry = 0;
    __syncthreads();
    for (int base = 0; base < NN; base += 256) {
        int j = base + tid;
        int f = (j < NN) ? g_sel[j] : 0;
        int xv = f;
        #pragma unroll
        for (int o = 1; o < 32; o <<= 1) {
            int y = __shfl_up_sync(0xffffffffu, xv, o);
            if (lane >= o) xv += y;
        }
        if (lane == 31) wsum[wid] = xv;
        __syncthreads();
        int woff = 0;
        #pragma unroll
        for (int w = 0; w < 8; w++) if (w < wid) woff += wsum[w];
        int incl = xv + woff;
        int pos = carry + incl - f;
        if (f) {
            g_idx[pos] = j;
            out[IDX_OFF + pos] = (float)j;
        }
        __syncthreads();
        if (tid == 255) carry += incl;
        __syncthreads();
    }
}

// ---------------- 8) x_pool gather ----------------
__global__ __launch_bounds__(128) void gather_x_kernel(float* __restrict__ out) {
    int r = blockIdx.x;
    int d = threadIdx.x;
    int ir = g_idx[r];
    out[XP_OFF + (size_t)r * DD + d] = g_h[(size_t)ir * DD + d];
}

// ---------------- 9) adjacency/motif pool gathers ----------------
__global__ __launch_bounds__(256) void gather_pools_kernel(const float* __restrict__ adj,
                                                           const float* __restrict__ motif,
                                                           float* __restrict__ out) {
    int r = blockIdx.x;
    int ir = g_idx[r];
    const float* arow = adj   + (size_t)ir * NN;
    const float* mrow = motif + (size_t)ir * NN;
    float* oa = out + ADJ_OFF + (size_t)r * KSEL;
    float* om = out + MOT_OFF + (size_t)r * KSEL;
    for (int c = threadIdx.x; c < KSEL; c += 256) {
        int ic = g_idx[c];
        oa[c] = arow[ic];
        om[c] = mrow[ic];
    }
}

// ---------------- launch ----------------
extern "C" void kernel_launch(void* const* d_in, const int* in_sizes, int n_in,
                              void* d_out, int out_size) {
    const float* x       = (const float*)d_in[0];
    const float* adj     = (const float*)d_in[1];
    const float* motif   = (const float*)d_in[2];
    const float* W       = (const float*)d_in[3];
    const float* b_gcn   = (const float*)d_in[4];
    const float* w_score = (const float*)d_in[5];
    const float* b_score = (const float*)d_in[6];
    float* out = (float*)d_out;

    colsum_kernel<<<dim3((NN + 255) / 256, 8), 256>>>(motif);
    dinv_kernel<<<(NN + 255) / 256, 256>>>();
    compute_P_kernel<<<NN / 16, 128>>>(x, W);
    hmma_gemm_kernel<<<dim3(NJT, NSPLIT), 256, 49152>>>(motif);
    epilogue_kernel<<<NN, 128>>>(b_gcn, w_score, b_score, out);
    topk_rank_kernel<<<(NN + 255) / 256, 256>>>();
    compact_kernel<<<1, 256>>>(out);
    gather_x_kernel<<<KSEL, 128>>>(out);
    gather_pools_kernel<<<KSEL, 256>>>(adj, motif, out);
}